// round 1
// baseline (speedup 1.0000x reference)
#include <cuda_runtime.h>
#include <math.h>

// Problem constants
#define NTOT 50000
#define EDIM 1000
#define DIN  256
#define DM   256
#define HEADS 4
#define MF   30
#define LNUM 3

// ---------------------------------------------------------------------------
// Scratch (device globals — no allocations allowed)
// ---------------------------------------------------------------------------
__device__ float g_z [NTOT * DM];                 // 51.2 MB
__device__ float g_Q [NTOT * HEADS * DM];         // 204.8 MB
__device__ float g_K [NTOT * HEADS * DM];
__device__ float g_V [NTOT * HEADS * DM];
__device__ float g_Zb[NTOT * HEADS * DM];
__device__ float g_Qp[NTOT * HEADS * MF];         // 24 MB
__device__ float g_Kp[NTOT * HEADS * MF];
__device__ float g_KV[HEADS * MF * DM];           // 120 KB
__device__ float g_Ks[HEADS * MF];

// ---------------------------------------------------------------------------
// Generic fp32 SGEMM: C[M x Nn] = A[M x K] @ B[K x Nn] + bias (+ C if acc)
// BM=BN=128, BK=8, 256 threads, 8x8 per thread. Requires Nn%128==0, K%8==0.
// ---------------------------------------------------------------------------
__global__ __launch_bounds__(256, 2)
void sgemm_kernel(const float* __restrict__ A, const float* __restrict__ B,
                  float* __restrict__ C, const float* __restrict__ bias,
                  int M, int Nn, int K, int accumulate)
{
    __shared__ float As[8][128];
    __shared__ float Bs[8][128];

    const int tid = threadIdx.x;
    const int tx = tid & 15;          // 0..15  -> N direction (x8)
    const int ty = tid >> 4;          // 0..15  -> M direction (x8)
    const int row0 = blockIdx.y * 128;
    const int col0 = blockIdx.x * 128;

    // A tile loader: 2 threads per row, one float4 each
    const int aRow  = tid >> 1;       // 0..127
    const int aCol4 = (tid & 1) * 4;  // 0 or 4
    // B tile loader: 32 threads per k-row, one float4 each
    const int bRow  = tid >> 5;       // 0..7
    const int bCol4 = (tid & 31) * 4; // 0..124

    float acc[8][8];
#pragma unroll
    for (int i = 0; i < 8; i++)
#pragma unroll
        for (int j = 0; j < 8; j++) acc[i][j] = 0.f;

    for (int k0 = 0; k0 < K; k0 += 8) {
        float4 av;
        const int ar = row0 + aRow;
        if (ar < M) av = *(const float4*)(A + (size_t)ar * K + k0 + aCol4);
        else        av = make_float4(0.f, 0.f, 0.f, 0.f);
        As[aCol4 + 0][aRow] = av.x;
        As[aCol4 + 1][aRow] = av.y;
        As[aCol4 + 2][aRow] = av.z;
        As[aCol4 + 3][aRow] = av.w;

        float4 bv = *(const float4*)(B + (size_t)(k0 + bRow) * Nn + col0 + bCol4);
        *(float4*)&Bs[bRow][bCol4] = bv;

        __syncthreads();
#pragma unroll
        for (int k = 0; k < 8; k++) {
            float4 a0 = *(const float4*)&As[k][ty * 8];
            float4 a1 = *(const float4*)&As[k][ty * 8 + 4];
            float4 b0 = *(const float4*)&Bs[k][tx * 8];
            float4 b1 = *(const float4*)&Bs[k][tx * 8 + 4];
            float ra[8] = {a0.x, a0.y, a0.z, a0.w, a1.x, a1.y, a1.z, a1.w};
            float rb[8] = {b0.x, b0.y, b0.z, b0.w, b1.x, b1.y, b1.z, b1.w};
#pragma unroll
            for (int i = 0; i < 8; i++)
#pragma unroll
                for (int j = 0; j < 8; j++)
                    acc[i][j] = fmaf(ra[i], rb[j], acc[i][j]);
        }
        __syncthreads();
    }

#pragma unroll
    for (int i = 0; i < 8; i++) {
        const int r = row0 + ty * 8 + i;
        if (r >= M) continue;
#pragma unroll
        for (int j = 0; j < 8; j += 4) {
            const int c = col0 + tx * 8 + j;
            float4 v = make_float4(acc[i][j], acc[i][j+1], acc[i][j+2], acc[i][j+3]);
            if (bias) {
                v.x += bias[c];   v.y += bias[c+1];
                v.z += bias[c+2]; v.w += bias[c+3];
            }
            float* cp = C + (size_t)r * Nn + c;
            if (accumulate) {
                float4 o = *(float4*)cp;
                v.x += o.x; v.y += o.y; v.z += o.z; v.w += o.w;
            }
            *(float4*)cp = v;
        }
    }
}

// ---------------------------------------------------------------------------
// LayerNorm + ELU: one warp per row of 256
// ---------------------------------------------------------------------------
__global__ void ln_elu_kernel(const float* __restrict__ h,
                              const float* __restrict__ gamma,
                              const float* __restrict__ beta,
                              float* __restrict__ z)
{
    const int gw   = blockIdx.x * (blockDim.x >> 5) + (threadIdx.x >> 5);
    const int lane = threadIdx.x & 31;
    if (gw >= NTOT) return;

    const float4* hp = (const float4*)(h + (size_t)gw * DM);
    float4 v0 = hp[lane * 2];
    float4 v1 = hp[lane * 2 + 1];
    float vv[8] = {v0.x, v0.y, v0.z, v0.w, v1.x, v1.y, v1.z, v1.w};

    float s = 0.f;
#pragma unroll
    for (int i = 0; i < 8; i++) s += vv[i];
#pragma unroll
    for (int o = 16; o; o >>= 1) s += __shfl_xor_sync(0xffffffffu, s, o);
    const float mean = s * (1.0f / DM);

    float sq = 0.f;
#pragma unroll
    for (int i = 0; i < 8; i++) { float d = vv[i] - mean; sq = fmaf(d, d, sq); }
#pragma unroll
    for (int o = 16; o; o >>= 1) sq += __shfl_xor_sync(0xffffffffu, sq, o);
    const float inv = rsqrtf(sq * (1.0f / DM) + 1e-5f);

    const int c = lane * 8;
    float out[8];
#pragma unroll
    for (int i = 0; i < 8; i++) {
        float t = (vv[i] - mean) * inv * gamma[c + i] + beta[c + i];
        out[i] = (t > 0.f) ? t : expm1f(t);
    }
    float4* zp = (float4*)(z + (size_t)gw * DM);
    zp[lane * 2]     = make_float4(out[0], out[1], out[2], out[3]);
    zp[lane * 2 + 1] = make_float4(out[4], out[5], out[6], out[7]);
}

// ---------------------------------------------------------------------------
// FAVOR+ feature map: out[r, m] = exp(c * dot(data[r,:], proj[m,:])) + 1e-6
// r ranges over N*HEADS flattened rows of length 256. 128 threads/block,
// one row per thread, k staged via shared in tiles of 32.
// ---------------------------------------------------------------------------
__global__ __launch_bounds__(128)
void feat_kernel(const float* __restrict__ data, const float* __restrict__ proj,
                 float* __restrict__ out, int R)
{
    __shared__ float projS[MF][DM];       // 30 KB (prescaled)
    __shared__ float dS[128][33];         // 16.9 KB (padded)

    const int tid = threadIdx.x;
    const int r0  = blockIdx.x * 128;
    const float c = 0.25f * 0.18257418583505536f;   // (1/d^{1/4}) * (1/sqrt(30))

    for (int i = tid; i < MF * DM; i += 128) projS[i / DM][i % DM] = c * proj[i];

    float acc[MF];
#pragma unroll
    for (int m = 0; m < MF; m++) acc[m] = 0.f;

    const int myr = r0 + tid;
    for (int k0 = 0; k0 < DM; k0 += 32) {
        __syncthreads();
        for (int i = tid; i < 128 * 32; i += 128) {
            const int r = i >> 5, k = i & 31;
            const int gr = r0 + r;
            dS[r][k] = (gr < R) ? data[(size_t)gr * DM + k0 + k] : 0.f;
        }
        __syncthreads();
#pragma unroll 4
        for (int k = 0; k < 32; k++) {
            const float v = dS[tid][k];
#pragma unroll
            for (int m = 0; m < MF; m++)
                acc[m] = fmaf(v, projS[m][k0 + k], acc[m]);
        }
    }
    if (myr < R) {
        float* op = out + (size_t)myr * MF;
#pragma unroll
        for (int m = 0; m < MF; m++) op[m] = expf(acc[m]) + 1e-6f;
    }
}

// ---------------------------------------------------------------------------
// Zero the KV / Ksum accumulators
// ---------------------------------------------------------------------------
__global__ void zero_kv_kernel()
{
    const int i = blockIdx.x * blockDim.x + threadIdx.x;
    if (i < HEADS * MF * DM) g_KV[i] = 0.f;
    if (i < HEADS * MF)      g_Ks[i] = 0.f;
}

// ---------------------------------------------------------------------------
// KV = sum_n Kp[n,h,m] * V[n,h,d]  -> [h, m, d];  Ksum = sum_n Kp  -> [h, m]
// blockIdx.x = n-chunk (128 rows), blockIdx.y = head. 256 threads, d = tid.
// ---------------------------------------------------------------------------
__global__ __launch_bounds__(256)
void kv_kernel(const float* __restrict__ Kp, const float* __restrict__ V)
{
    __shared__ float kpS[128][31];
    const int h   = blockIdx.y;
    const int n0  = blockIdx.x * 128;
    const int tid = threadIdx.x;
    const int rows = min(128, NTOT - n0);

    for (int i = tid; i < rows * MF; i += 256) {
        const int r = i / MF, m = i % MF;
        kpS[r][m] = Kp[((size_t)(n0 + r) * HEADS + h) * MF + m];
    }
    __syncthreads();

    float acc[MF];
#pragma unroll
    for (int m = 0; m < MF; m++) acc[m] = 0.f;

    for (int r = 0; r < rows; r++) {
        const float v = V[((size_t)(n0 + r) * HEADS + h) * DM + tid];
#pragma unroll
        for (int m = 0; m < MF; m++)
            acc[m] = fmaf(kpS[r][m], v, acc[m]);
    }
#pragma unroll
    for (int m = 0; m < MF; m++)
        atomicAdd(&g_KV[((size_t)h * MF + m) * DM + tid], acc[m]);

    if (tid < MF) {
        float s = 0.f;
        for (int r = 0; r < rows; r++) s += kpS[r][tid];
        atomicAdd(&g_Ks[h * MF + tid], s);
    }
}

// ---------------------------------------------------------------------------
// Z[n, h*256+d] = (sum_m Qp[n,h,m]*KV[h,m,d]) / (dot(Qp[n,h,:],Ksum[h,:])+1e-6)
// blockIdx.x = n-chunk (128), blockIdx.y = head. 256 threads, d = tid.
// KV tile for this head lives in registers (invariant over rows).
// ---------------------------------------------------------------------------
__global__ __launch_bounds__(256)
void z_kernel(const float* __restrict__ Qp, float* __restrict__ Z)
{
    __shared__ float qpS[128][31];
    __shared__ float ksS[MF];
    __shared__ float denS[128];

    const int h   = blockIdx.y;
    const int n0  = blockIdx.x * 128;
    const int tid = threadIdx.x;
    const int rows = min(128, NTOT - n0);

    float kv[MF];
#pragma unroll
    for (int m = 0; m < MF; m++)
        kv[m] = g_KV[((size_t)h * MF + m) * DM + tid];
    if (tid < MF) ksS[tid] = g_Ks[h * MF + tid];

    for (int i = tid; i < rows * MF; i += 256) {
        const int r = i / MF, m = i % MF;
        qpS[r][m] = Qp[((size_t)(n0 + r) * HEADS + h) * MF + m];
    }
    __syncthreads();

    if (tid < rows) {
        float s = 0.f;
#pragma unroll
        for (int m = 0; m < MF; m++) s = fmaf(qpS[tid][m], ksS[m], s);
        denS[tid] = s + 1e-6f;
    }
    __syncthreads();

    for (int r = 0; r < rows; r++) {
        float a = 0.f;
#pragma unroll
        for (int m = 0; m < MF; m++) a = fmaf(qpS[r][m], kv[m], a);
        Z[((size_t)(n0 + r) * HEADS + h) * DM + tid] = a / denS[r];
    }
}

// ---------------------------------------------------------------------------
// Launch
// ---------------------------------------------------------------------------
extern "C" void kernel_launch(void* const* d_in, const int* in_sizes, int n_in,
                              void* d_out, int out_size)
{
    const float* x    = (const float*)d_in[0];
    const float* H    = (const float*)d_in[1];
    const float* proj = (const float*)d_in[2];
    const float* W_in = (const float*)d_in[3];
    const float* b_in = (const float*)d_in[4];
    const float* W_he = (const float*)d_in[5];
    const float* b_he = (const float*)d_in[6];
    const float* ln_g = (const float*)d_in[7];
    const float* ln_b = (const float*)d_in[8];
    const float* Wq   = (const float*)d_in[9];
    const float* bq   = (const float*)d_in[10];
    const float* Wk   = (const float*)d_in[11];
    const float* bk   = (const float*)d_in[12];
    const float* Wv   = (const float*)d_in[13];
    const float* bv   = (const float*)d_in[14];
    const float* Wo   = (const float*)d_in[15];
    const float* bo   = (const float*)d_in[16];

    float* h = (float*)d_out;   // residual stream lives in the output buffer

    float *z, *Q, *K, *V, *Zb, *Qp, *Kp;
    cudaGetSymbolAddress((void**)&z,  g_z);
    cudaGetSymbolAddress((void**)&Q,  g_Q);
    cudaGetSymbolAddress((void**)&K,  g_K);
    cudaGetSymbolAddress((void**)&V,  g_V);
    cudaGetSymbolAddress((void**)&Zb, g_Zb);
    cudaGetSymbolAddress((void**)&Qp, g_Qp);
    cudaGetSymbolAddress((void**)&Kp, g_Kp);

    const int MB = (NTOT + 127) / 128;     // 391
    const dim3 gN256(DM / 128, MB);        // Nn = 256
    const dim3 gN1024(HEADS * DM / 128, MB); // Nn = 1024
    const dim3 gHead(MB, HEADS);

    // h = x @ W_in + b_in
    sgemm_kernel<<<gN256, 256>>>(x, W_in, h, b_in, NTOT, DM, DIN, 0);
    // h += H @ W_he + b_he
    sgemm_kernel<<<gN256, 256>>>(H, W_he, h, b_he, NTOT, DM, EDIM, 1);

    const int R = NTOT * HEADS;
    const int featBlocks = (R + 127) / 128;

    for (int l = 0; l < LNUM; l++) {
        // z = elu(layernorm(h))
        ln_elu_kernel<<<(NTOT + 7) / 8, 256>>>(h, ln_g + l * DM, ln_b + l * DM, z);

        // Q/K/V = z @ W + b
        sgemm_kernel<<<gN1024, 256>>>(z, Wq + (size_t)l * DM * HEADS * DM, Q,
                                      bq + (size_t)l * HEADS * DM, NTOT, HEADS * DM, DM, 0);
        sgemm_kernel<<<gN1024, 256>>>(z, Wk + (size_t)l * DM * HEADS * DM, K,
                                      bk + (size_t)l * HEADS * DM, NTOT, HEADS * DM, DM, 0);
        sgemm_kernel<<<gN1024, 256>>>(z, Wv + (size_t)l * DM * HEADS * DM, V,
                                      bv + (size_t)l * HEADS * DM, NTOT, HEADS * DM, DM, 0);

        // FAVOR+ feature maps
        feat_kernel<<<featBlocks, 128>>>(Q, proj, Qp, R);
        feat_kernel<<<featBlocks, 128>>>(K, proj, Kp, R);

        // KV / Ksum reductions
        zero_kv_kernel<<<(HEADS * MF * DM + 255) / 256, 256>>>();
        kv_kernel<<<gHead, 256>>>(Kp, V);

        // Z = (Qp @ KV) / (Qp @ Ksum + 1e-6)
        z_kernel<<<gHead, 256>>>(Qp, Zb);

        // h += Z @ Wo + bo
        sgemm_kernel<<<gN256, 256>>>(Zb, Wo + (size_t)l * HEADS * DM * DM, h,
                                     bo + (size_t)l * DM, NTOT, DM, HEADS * DM, 1);
    }
}

// round 4
// speedup vs baseline: 1.4571x; 1.4571x over previous
#include <cuda_runtime.h>
#include <math.h>
#include <stdint.h>
#include <mma.h>

using namespace nvcuda;

// Problem constants
#define NTOT 50000
#define EDIM 1000
#define DM   256
#define HEADS 4
#define MF   30
#define LNUM 3

// ---------------------------------------------------------------------------
// Scratch (device globals — no allocations allowed)
// ---------------------------------------------------------------------------
__device__ float g_z [NTOT * DM];
__device__ float g_Q [NTOT * HEADS * DM];
__device__ float g_K [NTOT * HEADS * DM];
__device__ float g_V [NTOT * HEADS * DM];
__device__ float g_Zb[NTOT * HEADS * DM];
__device__ float g_Qp[NTOT * HEADS * MF];
__device__ float g_Kp[NTOT * HEADS * MF];
__device__ float g_KV[HEADS * MF * DM];
__device__ float g_Ks[HEADS * MF];
// transposed weights (K-major [Nn, K])
__device__ float g_WT[3467264];

#define WT_IN   0
#define WT_HE   65536
#define WT_Q(l) (321536  + (l) * 262144)
#define WT_K(l) (1107968 + (l) * 262144)
#define WT_V(l) (1894400 + (l) * 262144)
#define WT_O(l) (2680832 + (l) * 262144)

// ---------------------------------------------------------------------------
// cp.async helpers (base ISA, sm_80+)
// ---------------------------------------------------------------------------
__device__ __forceinline__ uint32_t smem_u32(const void* p) {
    uint32_t a;
    asm("{ .reg .u64 t; cvta.to.shared.u64 t, %1; cvt.u32.u64 %0, t; }"
        : "=r"(a) : "l"(p));
    return a;
}

__device__ __forceinline__ void cpasync16(uint32_t dst, const void* src, int srcsize) {
    asm volatile("cp.async.cg.shared.global [%0], [%1], 16, %2;"
        :: "r"(dst), "l"(src), "r"(srcsize) : "memory");
}
#define CP_COMMIT() asm volatile("cp.async.commit_group;" ::: "memory")
#define CP_WAIT1()  asm volatile("cp.async.wait_group 1;" ::: "memory")

// ---------------------------------------------------------------------------
// WMMA TF32 GEMM: C[M x Nn] = A[M x K] @ Bt^T + bias (+C if acc)
//   A  : [M, K]  row-major fp32
//   Bt : [Nn, K] row-major fp32 (K-major == wmma col_major B)
//   Nn % 128 == 0, K % 4 == 0. Block tile 128 x 128, BK = 32, 8 warps.
// ---------------------------------------------------------------------------
#define BK 32
#define ROWF 36                       // padded row pitch in floats
#define STAGE_F (2 * 128 * ROWF)      // A + B per stage (floats)
#define GEMM_SMEM 73728               // max(2 stages * 36KB, Cs 128*132*4)

__global__ __launch_bounds__(256, 2)
void gemm_tc(const float* __restrict__ A, const float* __restrict__ Bt,
             float* __restrict__ C, const float* __restrict__ bias,
             int M, int Nn, int K, int accumulate)
{
    extern __shared__ __align__(16) float smem[];

    const int tid  = threadIdx.x;
    const int wid  = tid >> 5;
    const int wm   = wid & 1;          // 0..1 -> 64-row slab
    const int wn   = wid >> 1;         // 0..3 -> 32-col slab
    const int row0 = blockIdx.y * 128;
    const int col0 = blockIdx.x * 128;

    const int T = (K + BK - 1) / BK;

    wmma::fragment<wmma::accumulator, 16, 16, 8, float> acc[4][2];
#pragma unroll
    for (int i = 0; i < 4; i++)
#pragma unroll
        for (int j = 0; j < 2; j++) wmma::fill_fragment(acc[i][j], 0.f);

    // tile loader: tile tt -> stage ss
    auto load_tile = [&](int tt, int ss) {
        float* As = smem + ss * STAGE_F;
        float* Bs = As + 128 * ROWF;
        const uint32_t asb = smem_u32(As);
        const uint32_t bsb = smem_u32(Bs);
        const int kbase = tt * BK;
#pragma unroll
        for (int i = 0; i < 4; i++) {          // A: 1024 16B chunks
            const int id  = tid + i * 256;
            const int row = id >> 3, c = id & 7;
            const int gr = row0 + row;
            const int gk = kbase + c * 4;
            const int ok = (gr < M) && (gk + 4 <= K);
            const float* src = ok ? (A + (size_t)gr * K + gk) : A;
            cpasync16(asb + (row * ROWF + c * 4) * 4, src, ok ? 16 : 0);
        }
#pragma unroll
        for (int i = 0; i < 4; i++) {          // B: 1024 16B chunks
            const int id  = tid + i * 256;
            const int row = id >> 3, c = id & 7;
            const int gn = col0 + row;
            const int gk = kbase + c * 4;
            const int ok = (gk + 4 <= K);
            const float* src = ok ? (Bt + (size_t)gn * K + gk) : Bt;
            cpasync16(bsb + (row * ROWF + c * 4) * 4, src, ok ? 16 : 0);
        }
    };

    load_tile(0, 0);
    CP_COMMIT();

    for (int t = 0; t < T; t++) {
        if (t + 1 < T) load_tile(t + 1, (t + 1) & 1);
        CP_COMMIT();
        CP_WAIT1();
        __syncthreads();

        const float* As = smem + (t & 1) * STAGE_F;
        const float* Bs = As + 128 * ROWF;

#pragma unroll
        for (int ks = 0; ks < 4; ks++) {
            const int k0 = ks * 8;
            wmma::fragment<wmma::matrix_a, 16, 16, 8, wmma::precision::tf32,
                           wmma::row_major> af[4];
            wmma::fragment<wmma::matrix_b, 16, 16, 8, wmma::precision::tf32,
                           wmma::col_major> bf[2];
#pragma unroll
            for (int i = 0; i < 4; i++) {
                wmma::load_matrix_sync(af[i], As + (wm * 64 + i * 16) * ROWF + k0, ROWF);
#pragma unroll
                for (int e = 0; e < af[i].num_elements; e++)
                    af[i].x[e] = wmma::__float_to_tf32(af[i].x[e]);
            }
#pragma unroll
            for (int j = 0; j < 2; j++) {
                wmma::load_matrix_sync(bf[j], Bs + (wn * 32 + j * 16) * ROWF + k0, ROWF);
#pragma unroll
                for (int e = 0; e < bf[j].num_elements; e++)
                    bf[j].x[e] = wmma::__float_to_tf32(bf[j].x[e]);
            }
#pragma unroll
            for (int i = 0; i < 4; i++)
#pragma unroll
                for (int j = 0; j < 2; j++)
                    wmma::mma_sync(acc[i][j], af[i], bf[j], acc[i][j]);
        }
        __syncthreads();
    }

    // ---- epilogue: stage C tile in smem, then bias/accumulate to global ----
    float* Cs = smem;                  // 128 x 132 floats
#pragma unroll
    for (int i = 0; i < 4; i++)
#pragma unroll
        for (int j = 0; j < 2; j++)
            wmma::store_matrix_sync(Cs + (wm * 64 + i * 16) * 132 + wn * 32 + j * 16,
                                    acc[i][j], 132, wmma::mem_row_major);
    __syncthreads();

    const int r    = tid >> 1;         // 0..127
    const int half = tid & 1;          // 0..1 -> 64-col half
    const int gr   = row0 + r;
    if (gr < M) {
        float* cp = C + (size_t)gr * Nn + col0 + half * 64;
        const float* bp = bias + col0 + half * 64;
        const float* sp = Cs + r * 132 + half * 64;
#pragma unroll
        for (int j = 0; j < 16; j++) {
            float4 v = *(const float4*)(sp + j * 4);
            float4 bv = *(const float4*)(bp + j * 4);
            v.x += bv.x; v.y += bv.y; v.z += bv.z; v.w += bv.w;
            if (accumulate) {
                float4 o = *(float4*)(cp + j * 4);
                v.x += o.x; v.y += o.y; v.z += o.z; v.w += o.w;
            }
            *(float4*)(cp + j * 4) = v;
        }
    }
}

// ---------------------------------------------------------------------------
// Weight transpose: out[Nn x K] = in[K x Nn]^T
// ---------------------------------------------------------------------------
__global__ void transpose_kernel(const float* __restrict__ in, float* __restrict__ out,
                                 int K, int Nn)
{
    __shared__ float tile[32][33];
    const int k0 = blockIdx.x * 32, n0 = blockIdx.y * 32;
    const int tx = threadIdx.x, ty = threadIdx.y;
#pragma unroll
    for (int r = 0; r < 4; r++) {
        const int k = k0 + ty + r * 8;
        if (k < K && n0 + tx < Nn) tile[ty + r * 8][tx] = in[(size_t)k * Nn + n0 + tx];
    }
    __syncthreads();
#pragma unroll
    for (int r = 0; r < 4; r++) {
        const int n = n0 + ty + r * 8;
        if (n < Nn && k0 + tx < K) out[(size_t)n * K + k0 + tx] = tile[tx][ty + r * 8];
    }
}

// ---------------------------------------------------------------------------
// LayerNorm + ELU
// ---------------------------------------------------------------------------
__global__ void ln_elu_kernel(const float* __restrict__ h,
                              const float* __restrict__ gamma,
                              const float* __restrict__ beta,
                              float* __restrict__ z)
{
    const int gw   = blockIdx.x * (blockDim.x >> 5) + (threadIdx.x >> 5);
    const int lane = threadIdx.x & 31;
    if (gw >= NTOT) return;

    const float4* hp = (const float4*)(h + (size_t)gw * DM);
    float4 v0 = hp[lane * 2];
    float4 v1 = hp[lane * 2 + 1];
    float vv[8] = {v0.x, v0.y, v0.z, v0.w, v1.x, v1.y, v1.z, v1.w};

    float s = 0.f;
#pragma unroll
    for (int i = 0; i < 8; i++) s += vv[i];
#pragma unroll
    for (int o = 16; o; o >>= 1) s += __shfl_xor_sync(0xffffffffu, s, o);
    const float mean = s * (1.0f / DM);

    float sq = 0.f;
#pragma unroll
    for (int i = 0; i < 8; i++) { float d = vv[i] - mean; sq = fmaf(d, d, sq); }
#pragma unroll
    for (int o = 16; o; o >>= 1) sq += __shfl_xor_sync(0xffffffffu, sq, o);
    const float inv = rsqrtf(sq * (1.0f / DM) + 1e-5f);

    const int c = lane * 8;
    float out[8];
#pragma unroll
    for (int i = 0; i < 8; i++) {
        float t = (vv[i] - mean) * inv * gamma[c + i] + beta[c + i];
        out[i] = (t > 0.f) ? t : expm1f(t);
    }
    float4* zp = (float4*)(z + (size_t)gw * DM);
    zp[lane * 2]     = make_float4(out[0], out[1], out[2], out[3]);
    zp[lane * 2 + 1] = make_float4(out[4], out[5], out[6], out[7]);
}

// ---------------------------------------------------------------------------
// FAVOR+ feature map
// ---------------------------------------------------------------------------
__global__ __launch_bounds__(128)
void feat_kernel(const float* __restrict__ data, const float* __restrict__ proj,
                 float* __restrict__ out, int R)
{
    __shared__ float projS[MF][DM];
    __shared__ float dS[128][33];

    const int tid = threadIdx.x;
    const int r0  = blockIdx.x * 128;
    const float c = 0.25f * 0.18257418583505536f;

    for (int i = tid; i < MF * DM; i += 128) projS[i / DM][i % DM] = c * proj[i];

    float acc[MF];
#pragma unroll
    for (int m = 0; m < MF; m++) acc[m] = 0.f;

    const int myr = r0 + tid;
    for (int k0 = 0; k0 < DM; k0 += 32) {
        __syncthreads();
        for (int i = tid; i < 128 * 32; i += 128) {
            const int r = i >> 5, k = i & 31;
            const int gr = r0 + r;
            dS[r][k] = (gr < R) ? data[(size_t)gr * DM + k0 + k] : 0.f;
        }
        __syncthreads();
#pragma unroll 4
        for (int k = 0; k < 32; k++) {
            const float v = dS[tid][k];
#pragma unroll
            for (int m = 0; m < MF; m++)
                acc[m] = fmaf(v, projS[m][k0 + k], acc[m]);
        }
    }
    if (myr < R) {
        float* op = out + (size_t)myr * MF;
#pragma unroll
        for (int m = 0; m < MF; m++) op[m] = expf(acc[m]) + 1e-6f;
    }
}

// ---------------------------------------------------------------------------
// Zero KV / Ksum
// ---------------------------------------------------------------------------
__global__ void zero_kv_kernel()
{
    const int i = blockIdx.x * blockDim.x + threadIdx.x;
    if (i < HEADS * MF * DM) g_KV[i] = 0.f;
    if (i < HEADS * MF)      g_Ks[i] = 0.f;
}

// ---------------------------------------------------------------------------
// KV = sum_n Kp ⊗ V ; Ksum = sum_n Kp
// ---------------------------------------------------------------------------
__global__ __launch_bounds__(256)
void kv_kernel(const float* __restrict__ Kp, const float* __restrict__ V)
{
    __shared__ float kpS[128][31];
    const int h   = blockIdx.y;
    const int n0  = blockIdx.x * 128;
    const int tid = threadIdx.x;
    const int rows = min(128, NTOT - n0);

    for (int i = tid; i < rows * MF; i += 256) {
        const int r = i / MF, m = i % MF;
        kpS[r][m] = Kp[((size_t)(n0 + r) * HEADS + h) * MF + m];
    }
    __syncthreads();

    float acc[MF];
#pragma unroll
    for (int m = 0; m < MF; m++) acc[m] = 0.f;

    for (int r = 0; r < rows; r++) {
        const float v = V[((size_t)(n0 + r) * HEADS + h) * DM + tid];
#pragma unroll
        for (int m = 0; m < MF; m++)
            acc[m] = fmaf(kpS[r][m], v, acc[m]);
    }
#pragma unroll
    for (int m = 0; m < MF; m++)
        atomicAdd(&g_KV[((size_t)h * MF + m) * DM + tid], acc[m]);

    if (tid < MF) {
        float s = 0.f;
        for (int r = 0; r < rows; r++) s += kpS[r][tid];
        atomicAdd(&g_Ks[h * MF + tid], s);
    }
}

// ---------------------------------------------------------------------------
// Z = (Qp @ KV) / (Qp @ Ksum + 1e-6)
// ---------------------------------------------------------------------------
__global__ __launch_bounds__(256)
void z_kernel(const float* __restrict__ Qp, float* __restrict__ Z)
{
    __shared__ float qpS[128][31];
    __shared__ float ksS[MF];
    __shared__ float denS[128];

    const int h   = blockIdx.y;
    const int n0  = blockIdx.x * 128;
    const int tid = threadIdx.x;
    const int rows = min(128, NTOT - n0);

    float kv[MF];
#pragma unroll
    for (int m = 0; m < MF; m++)
        kv[m] = g_KV[((size_t)h * MF + m) * DM + tid];
    if (tid < MF) ksS[tid] = g_Ks[h * MF + tid];

    for (int i = tid; i < rows * MF; i += 256) {
        const int r = i / MF, m = i % MF;
        qpS[r][m] = Qp[((size_t)(n0 + r) * HEADS + h) * MF + m];
    }
    __syncthreads();

    if (tid < rows) {
        float s = 0.f;
#pragma unroll
        for (int m = 0; m < MF; m++) s = fmaf(qpS[tid][m], ksS[m], s);
        denS[tid] = s + 1e-6f;
    }
    __syncthreads();

    for (int r = 0; r < rows; r++) {
        float a = 0.f;
#pragma unroll
        for (int m = 0; m < MF; m++) a = fmaf(qpS[r][m], kv[m], a);
        Z[((size_t)(n0 + r) * HEADS + h) * DM + tid] = a / denS[r];
    }
}

// ---------------------------------------------------------------------------
// Launch
// ---------------------------------------------------------------------------
extern "C" void kernel_launch(void* const* d_in, const int* in_sizes, int n_in,
                              void* d_out, int out_size)
{
    const float* x    = (const float*)d_in[0];
    const float* H    = (const float*)d_in[1];
    const float* proj = (const float*)d_in[2];
    const float* W_in = (const float*)d_in[3];
    const float* b_in = (const float*)d_in[4];
    const float* W_he = (const float*)d_in[5];
    const float* b_he = (const float*)d_in[6];
    const float* ln_g = (const float*)d_in[7];
    const float* ln_b = (const float*)d_in[8];
    const float* Wq   = (const float*)d_in[9];
    const float* bq   = (const float*)d_in[10];
    const float* Wk   = (const float*)d_in[11];
    const float* bk   = (const float*)d_in[12];
    const float* Wv   = (const float*)d_in[13];
    const float* bv   = (const float*)d_in[14];
    const float* Wo   = (const float*)d_in[15];
    const float* bo   = (const float*)d_in[16];

    float* h = (float*)d_out;

    static int smem_set = 0;
    if (!smem_set) {
        cudaFuncSetAttribute(gemm_tc, cudaFuncAttributeMaxDynamicSharedMemorySize,
                             GEMM_SMEM);
        smem_set = 1;
    }

    float *z, *Q, *K, *V, *Zb, *Qp, *Kp, *WT;
    cudaGetSymbolAddress((void**)&z,  g_z);
    cudaGetSymbolAddress((void**)&Q,  g_Q);
    cudaGetSymbolAddress((void**)&K,  g_K);
    cudaGetSymbolAddress((void**)&V,  g_V);
    cudaGetSymbolAddress((void**)&Zb, g_Zb);
    cudaGetSymbolAddress((void**)&Qp, g_Qp);
    cudaGetSymbolAddress((void**)&Kp, g_Kp);
    cudaGetSymbolAddress((void**)&WT, g_WT);

    // weight transposes -> K-major
    {
        dim3 b(32, 8);
        transpose_kernel<<<dim3(8, 8), b>>>(W_in, WT + WT_IN, 256, 256);
        transpose_kernel<<<dim3((EDIM + 31) / 32, 8), b>>>(W_he, WT + WT_HE, EDIM, 256);
        for (int l = 0; l < LNUM; l++) {
            const size_t wofs = (size_t)l * DM * HEADS * DM;
            transpose_kernel<<<dim3(8, 32), b>>>(Wq + wofs, WT + WT_Q(l), 256, 1024);
            transpose_kernel<<<dim3(8, 32), b>>>(Wk + wofs, WT + WT_K(l), 256, 1024);
            transpose_kernel<<<dim3(8, 32), b>>>(Wv + wofs, WT + WT_V(l), 256, 1024);
            transpose_kernel<<<dim3(32, 8), b>>>(Wo + wofs, WT + WT_O(l), 1024, 256);
        }
    }

    const int MB = (NTOT + 127) / 128;
    const dim3 g256(2, MB);      // Nn = 256
    const dim3 g1024(8, MB);     // Nn = 1024
    const dim3 gHead(MB, HEADS);

    gemm_tc<<<g256, 256, GEMM_SMEM>>>(x, WT + WT_IN, h, b_in, NTOT, 256, 256, 0);
    gemm_tc<<<g256, 256, GEMM_SMEM>>>(H, WT + WT_HE, h, b_he, NTOT, 256, EDIM, 1);

    const int R = NTOT * HEADS;
    const int featBlocks = (R + 127) / 128;

    for (int l = 0; l < LNUM; l++) {
        ln_elu_kernel<<<(NTOT + 7) / 8, 256>>>(h, ln_g + l * DM, ln_b + l * DM, z);

        gemm_tc<<<g1024, 256, GEMM_SMEM>>>(z, WT + WT_Q(l), Q, bq + (size_t)l * 1024, NTOT, 1024, 256, 0);
        gemm_tc<<<g1024, 256, GEMM_SMEM>>>(z, WT + WT_K(l), K, bk + (size_t)l * 1024, NTOT, 1024, 256, 0);
        gemm_tc<<<g1024, 256, GEMM_SMEM>>>(z, WT + WT_V(l), V, bv + (size_t)l * 1024, NTOT, 1024, 256, 0);

        feat_kernel<<<featBlocks, 128>>>(Q, proj, Qp, R);
        feat_kernel<<<featBlocks, 128>>>(K, proj, Kp, R);

        zero_kv_kernel<<<(HEADS * MF * DM + 255) / 256, 256>>>();
        kv_kernel<<<gHead, 256>>>(Kp, V);
        z_kernel<<<gHead, 256>>>(Qp, Zb);

        gemm_tc<<<g256, 256, GEMM_SMEM>>>(Zb, WT + WT_O(l), h, bo + (size_t)l * DM, NTOT, 256, 1024, 1);
    }
}

// round 9
// speedup vs baseline: 2.4903x; 1.7091x over previous
#include <cuda_runtime.h>
#include <math.h>
#include <stdint.h>
#include <mma.h>

using namespace nvcuda;

// Problem constants
#define NTOT 50000
#define EDIM 1000
#define DM   256
#define HEADS 4
#define MF   30
#define LNUM 3
#define NF   (HEADS * MF)          // 120 feature columns

// ---------------------------------------------------------------------------
// Scratch (device globals — no allocations allowed)
// ---------------------------------------------------------------------------
__device__ float g_z [NTOT * DM];
__device__ float g_V [NTOT * HEADS * DM];
__device__ float g_Zb[NTOT * HEADS * DM];
__device__ float g_Qp[NTOT * NF];
__device__ float g_Kp[NTOT * NF];
__device__ float g_KV[HEADS * MF * DM];
__device__ float g_Ks[HEADS * MF];
// transposed / folded weights
__device__ float g_WT[2079440];

#define WT_IN   0
#define WT_HE   65536
#define WT_V(l) (321536  + (l) * 262144)
#define WT_O(l) (1107968 + (l) * 262144)
#define WQP(l)  (1894400 + (l) * 30720)
#define WKP(l)  (1986560 + (l) * 30720)
#define BQP(l)  (2078720 + (l) * 120)
#define BKP(l)  (2079080 + (l) * 120)

// ---------------------------------------------------------------------------
// cp.async helpers (base ISA, sm_80+)
// ---------------------------------------------------------------------------
__device__ __forceinline__ uint32_t smem_u32(const void* p) {
    uint32_t a;
    asm("{ .reg .u64 t; cvta.to.shared.u64 t, %1; cvt.u32.u64 %0, t; }"
        : "=r"(a) : "l"(p));
    return a;
}

__device__ __forceinline__ void cpasync16(uint32_t dst, const void* src, int srcsize) {
    asm volatile("cp.async.cg.shared.global [%0], [%1], 16, %2;"
        :: "r"(dst), "l"(src), "r"(srcsize) : "memory");
}
#define CP_COMMIT() asm volatile("cp.async.commit_group;" ::: "memory")
#define CP_WAIT1()  asm volatile("cp.async.wait_group 1;" ::: "memory")

// ---------------------------------------------------------------------------
// WMMA TF32 GEMM: C[M x Nn] = A[M x K] @ Bt^T (+bias) (+C) (or exp epilogue)
//   A  : [M, K]  row-major fp32
//   Bt : [Nn, K] row-major fp32 (K-major == wmma col_major B)
//   Block tile 128 x 128, BK = 32, 8 warps. K % 4 == 0.
//   mode: 0 = C = v + bias ; 1 = C += v + bias ; 2 = C = exp(v + bias) + 1e-6
//   Cstride = output row stride (elements).
// ---------------------------------------------------------------------------
#define BK 32
#define ROWF 36
#define STAGE_F (2 * 128 * ROWF)
#define GEMM_SMEM 73728

__global__ __launch_bounds__(256, 2)
void gemm_tc(const float* __restrict__ A, const float* __restrict__ Bt,
             float* __restrict__ C, const float* __restrict__ bias,
             int M, int Nn, int K, int Cstride, int mode)
{
    extern __shared__ __align__(16) float smem[];

    const int tid  = threadIdx.x;
    const int wid  = tid >> 5;
    const int wm   = wid & 1;
    const int wn   = wid >> 1;
    const int row0 = blockIdx.y * 128;
    const int col0 = blockIdx.x * 128;

    const int T = (K + BK - 1) / BK;

    wmma::fragment<wmma::accumulator, 16, 16, 8, float> acc[4][2];
#pragma unroll
    for (int i = 0; i < 4; i++)
#pragma unroll
        for (int j = 0; j < 2; j++) wmma::fill_fragment(acc[i][j], 0.f);

    auto load_tile = [&](int tt, int ss) {
        float* As = smem + ss * STAGE_F;
        float* Bs = As + 128 * ROWF;
        const uint32_t asb = smem_u32(As);
        const uint32_t bsb = smem_u32(Bs);
        const int kbase = tt * BK;
#pragma unroll
        for (int i = 0; i < 4; i++) {
            const int id  = tid + i * 256;
            const int row = id >> 3, c = id & 7;
            const int gr = row0 + row;
            const int gk = kbase + c * 4;
            const int ok = (gr < M) && (gk + 4 <= K);
            const float* src = ok ? (A + (size_t)gr * K + gk) : A;
            cpasync16(asb + (row * ROWF + c * 4) * 4, src, ok ? 16 : 0);
        }
#pragma unroll
        for (int i = 0; i < 4; i++) {
            const int id  = tid + i * 256;
            const int row = id >> 3, c = id & 7;
            const int gn = col0 + row;
            const int gk = kbase + c * 4;
            const int ok = (gn < Nn) && (gk + 4 <= K);
            const float* src = ok ? (Bt + (size_t)gn * K + gk) : Bt;
            cpasync16(bsb + (row * ROWF + c * 4) * 4, src, ok ? 16 : 0);
        }
    };

    load_tile(0, 0);
    CP_COMMIT();

    for (int t = 0; t < T; t++) {
        if (t + 1 < T) load_tile(t + 1, (t + 1) & 1);
        CP_COMMIT();
        CP_WAIT1();
        __syncthreads();

        const float* As = smem + (t & 1) * STAGE_F;
        const float* Bs = As + 128 * ROWF;

#pragma unroll
        for (int ks = 0; ks < 4; ks++) {
            const int k0 = ks * 8;
            wmma::fragment<wmma::matrix_a, 16, 16, 8, wmma::precision::tf32,
                           wmma::row_major> af[4];
            wmma::fragment<wmma::matrix_b, 16, 16, 8, wmma::precision::tf32,
                           wmma::col_major> bf[2];
#pragma unroll
            for (int i = 0; i < 4; i++) {
                wmma::load_matrix_sync(af[i], As + (wm * 64 + i * 16) * ROWF + k0, ROWF);
#pragma unroll
                for (int e = 0; e < af[i].num_elements; e++)
                    af[i].x[e] = wmma::__float_to_tf32(af[i].x[e]);
            }
#pragma unroll
            for (int j = 0; j < 2; j++) {
                wmma::load_matrix_sync(bf[j], Bs + (wn * 32 + j * 16) * ROWF + k0, ROWF);
#pragma unroll
                for (int e = 0; e < bf[j].num_elements; e++)
                    bf[j].x[e] = wmma::__float_to_tf32(bf[j].x[e]);
            }
#pragma unroll
            for (int i = 0; i < 4; i++)
#pragma unroll
                for (int j = 0; j < 2; j++)
                    wmma::mma_sync(acc[i][j], af[i], bf[j], acc[i][j]);
        }
        __syncthreads();
    }

    // epilogue via smem staging
    float* Cs = smem;                  // 128 x 132
#pragma unroll
    for (int i = 0; i < 4; i++)
#pragma unroll
        for (int j = 0; j < 2; j++)
            wmma::store_matrix_sync(Cs + (wm * 64 + i * 16) * 132 + wn * 32 + j * 16,
                                    acc[i][j], 132, wmma::mem_row_major);
    __syncthreads();

    const int r    = tid >> 1;
    const int half = tid & 1;
    const int gr   = row0 + r;
    if (gr < M) {
        const float* sp = Cs + r * 132 + half * 64;
#pragma unroll
        for (int j = 0; j < 16; j++) {
            const int cc = col0 + half * 64 + j * 4;
            if (cc + 4 > Nn) continue;
            float4 v = *(const float4*)(sp + j * 4);
            float4 bv = *(const float4*)(bias + cc);
            v.x += bv.x; v.y += bv.y; v.z += bv.z; v.w += bv.w;
            float* cp = C + (size_t)gr * Cstride + cc;
            if (mode == 1) {
                float4 o = *(float4*)cp;
                v.x += o.x; v.y += o.y; v.z += o.z; v.w += o.w;
            } else if (mode == 2) {
                v.x = __expf(v.x) + 1e-6f; v.y = __expf(v.y) + 1e-6f;
                v.z = __expf(v.z) + 1e-6f; v.w = __expf(v.w) + 1e-6f;
            }
            *(float4*)cp = v;
        }
    }
}

// ---------------------------------------------------------------------------
// Weight transpose: out[Nn x K] = in[K x Nn]^T
// ---------------------------------------------------------------------------
__global__ void transpose_kernel(const float* __restrict__ in, float* __restrict__ out,
                                 int K, int Nn)
{
    __shared__ float tile[32][33];
    const int k0 = blockIdx.x * 32, n0 = blockIdx.y * 32;
    const int tx = threadIdx.x, ty = threadIdx.y;
#pragma unroll
    for (int r = 0; r < 4; r++) {
        const int k = k0 + ty + r * 8;
        if (k < K && n0 + tx < Nn) tile[ty + r * 8][tx] = in[(size_t)k * Nn + n0 + tx];
    }
    __syncthreads();
#pragma unroll
    for (int r = 0; r < 4; r++) {
        const int n = n0 + ty + r * 8;
        if (n < Nn && k0 + tx < K) out[(size_t)n * K + k0 + tx] = tile[tx][ty + r * 8];
    }
}

// ---------------------------------------------------------------------------
// Fold FAVOR+ projection into QK weights:
//   Wout[h*MF+m, k] = c * sum_d W[k, h*256+d] * proj[m, d]
//   bout[h*MF+m]    = c * sum_d b[h*256+d]    * proj[m, d]
// grid = NF blocks, 256 threads (one per k)
// ---------------------------------------------------------------------------
__global__ __launch_bounds__(256)
void fold_proj_kernel(const float* __restrict__ W, const float* __restrict__ b,
                      const float* __restrict__ proj,
                      float* __restrict__ Wout, float* __restrict__ bout)
{
    __shared__ float ps[DM];
    const int nn = blockIdx.x;       // 0..119
    const int h = nn / MF, m = nn % MF;
    const int k = threadIdx.x;       // 0..255
    const float c = 0.25f * 0.18257418583505536f;
    ps[k] = c * proj[(size_t)m * DM + k];
    __syncthreads();

    float s = 0.f;
    const float* wp = W + (size_t)k * (HEADS * DM) + h * DM;
#pragma unroll 8
    for (int d = 0; d < DM; d++) s = fmaf(wp[d], ps[d], s);
    Wout[(size_t)nn * DM + k] = s;

    if (k == 0) {
        float sb = 0.f;
        const float* bp = b + h * DM;
        for (int d = 0; d < DM; d++) sb = fmaf(bp[d], ps[d], sb);
        bout[nn] = sb;
    }
}

// ---------------------------------------------------------------------------
// LayerNorm + ELU
// ---------------------------------------------------------------------------
__global__ void ln_elu_kernel(const float* __restrict__ h,
                              const float* __restrict__ gamma,
                              const float* __restrict__ beta,
                              float* __restrict__ z)
{
    const int gw   = blockIdx.x * (blockDim.x >> 5) + (threadIdx.x >> 5);
    const int lane = threadIdx.x & 31;
    if (gw >= NTOT) return;

    const float4* hp = (const float4*)(h + (size_t)gw * DM);
    float4 v0 = hp[lane * 2];
    float4 v1 = hp[lane * 2 + 1];
    float vv[8] = {v0.x, v0.y, v0.z, v0.w, v1.x, v1.y, v1.z, v1.w};

    float s = 0.f;
#pragma unroll
    for (int i = 0; i < 8; i++) s += vv[i];
#pragma unroll
    for (int o = 16; o; o >>= 1) s += __shfl_xor_sync(0xffffffffu, s, o);
    const float mean = s * (1.0f / DM);

    float sq = 0.f;
#pragma unroll
    for (int i = 0; i < 8; i++) { float d = vv[i] - mean; sq = fmaf(d, d, sq); }
#pragma unroll
    for (int o = 16; o; o >>= 1) sq += __shfl_xor_sync(0xffffffffu, sq, o);
    const float inv = rsqrtf(sq * (1.0f / DM) + 1e-5f);

    const int c = lane * 8;
    float out[8];
#pragma unroll
    for (int i = 0; i < 8; i++) {
        float t = (vv[i] - mean) * inv * gamma[c + i] + beta[c + i];
        out[i] = (t > 0.f) ? t : expm1f(t);
    }
    float4* zp = (float4*)(z + (size_t)gw * DM);
    zp[lane * 2]     = make_float4(out[0], out[1], out[2], out[3]);
    zp[lane * 2 + 1] = make_float4(out[4], out[5], out[6], out[7]);
}

// ---------------------------------------------------------------------------
// Zero KV / Ksum
// ---------------------------------------------------------------------------
__global__ void zero_kv_kernel()
{
    const int i = blockIdx.x * blockDim.x + threadIdx.x;
    if (i < HEADS * MF * DM) g_KV[i] = 0.f;
    if (i < HEADS * MF)      g_Ks[i] = 0.f;
}

// ---------------------------------------------------------------------------
// KV = sum_n Kp ⊗ V ; Ksum = sum_n Kp
// ---------------------------------------------------------------------------
__global__ __launch_bounds__(256)
void kv_kernel(const float* __restrict__ Kp, const float* __restrict__ V)
{
    __shared__ float kpS[128][31];
    const int h   = blockIdx.y;
    const int n0  = blockIdx.x * 128;
    const int tid = threadIdx.x;
    const int rows = min(128, NTOT - n0);

    for (int i = tid; i < rows * MF; i += 256) {
        const int r = i / MF, m = i % MF;
        kpS[r][m] = Kp[(size_t)(n0 + r) * NF + h * MF + m];
    }
    __syncthreads();

    float acc[MF];
#pragma unroll
    for (int m = 0; m < MF; m++) acc[m] = 0.f;

    for (int r = 0; r < rows; r++) {
        const float v = V[((size_t)(n0 + r) * HEADS + h) * DM + tid];
#pragma unroll
        for (int m = 0; m < MF; m++)
            acc[m] = fmaf(kpS[r][m], v, acc[m]);
    }
#pragma unroll
    for (int m = 0; m < MF; m++)
        atomicAdd(&g_KV[((size_t)h * MF + m) * DM + tid], acc[m]);

    if (tid < MF) {
        float s = 0.f;
        for (int r = 0; r < rows; r++) s += kpS[r][tid];
        atomicAdd(&g_Ks[h * MF + tid], s);
    }
}

// ---------------------------------------------------------------------------
// Z = (Qp @ KV) / (Qp @ Ksum + 1e-6)
// ---------------------------------------------------------------------------
__global__ __launch_bounds__(256)
void z_kernel(const float* __restrict__ Qp, float* __restrict__ Z)
{
    __shared__ float qpS[128][31];
    __shared__ float ksS[MF];
    __shared__ float denS[128];

    const int h   = blockIdx.y;
    const int n0  = blockIdx.x * 128;
    const int tid = threadIdx.x;
    const int rows = min(128, NTOT - n0);

    float kv[MF];
#pragma unroll
    for (int m = 0; m < MF; m++)
        kv[m] = g_KV[((size_t)h * MF + m) * DM + tid];
    if (tid < MF) ksS[tid] = g_Ks[h * MF + tid];

    for (int i = tid; i < rows * MF; i += 256) {
        const int r = i / MF, m = i % MF;
        qpS[r][m] = Qp[(size_t)(n0 + r) * NF + h * MF + m];
    }
    __syncthreads();

    if (tid < rows) {
        float s = 0.f;
#pragma unroll
        for (int m = 0; m < MF; m++) s = fmaf(qpS[tid][m], ksS[m], s);
        denS[tid] = s + 1e-6f;
    }
    __syncthreads();

    for (int r = 0; r < rows; r++) {
        float a = 0.f;
#pragma unroll
        for (int m = 0; m < MF; m++) a = fmaf(qpS[r][m], kv[m], a);
        Z[((size_t)(n0 + r) * HEADS + h) * DM + tid] = a / denS[r];
    }
}

// ---------------------------------------------------------------------------
// Launch
// ---------------------------------------------------------------------------
extern "C" void kernel_launch(void* const* d_in, const int* in_sizes, int n_in,
                              void* d_out, int out_size)
{
    const float* x    = (const float*)d_in[0];
    const float* H    = (const float*)d_in[1];
    const float* proj = (const float*)d_in[2];
    const float* W_in = (const float*)d_in[3];
    const float* b_in = (const float*)d_in[4];
    const float* W_he = (const float*)d_in[5];
    const float* b_he = (const float*)d_in[6];
    const float* ln_g = (const float*)d_in[7];
    const float* ln_b = (const float*)d_in[8];
    const float* Wq   = (const float*)d_in[9];
    const float* bq   = (const float*)d_in[10];
    const float* Wk   = (const float*)d_in[11];
    const float* bk   = (const float*)d_in[12];
    const float* Wv   = (const float*)d_in[13];
    const float* bv   = (const float*)d_in[14];
    const float* Wo   = (const float*)d_in[15];
    const float* bo   = (const float*)d_in[16];

    float* h = (float*)d_out;

    static int smem_set = 0;
    if (!smem_set) {
        cudaFuncSetAttribute(gemm_tc, cudaFuncAttributeMaxDynamicSharedMemorySize,
                             GEMM_SMEM);
        smem_set = 1;
    }

    float *z, *V, *Zb, *Qp, *Kp, *WT;
    cudaGetSymbolAddress((void**)&z,  g_z);
    cudaGetSymbolAddress((void**)&V,  g_V);
    cudaGetSymbolAddress((void**)&Zb, g_Zb);
    cudaGetSymbolAddress((void**)&Qp, g_Qp);
    cudaGetSymbolAddress((void**)&Kp, g_Kp);
    cudaGetSymbolAddress((void**)&WT, g_WT);

    // weight prep: transposes (K-major) + FAVOR+ folds
    {
        dim3 b(32, 8);
        transpose_kernel<<<dim3(8, 8), b>>>(W_in, WT + WT_IN, 256, 256);
        transpose_kernel<<<dim3((EDIM + 31) / 32, 8), b>>>(W_he, WT + WT_HE, EDIM, 256);
        for (int l = 0; l < LNUM; l++) {
            const size_t wofs = (size_t)l * DM * HEADS * DM;
            transpose_kernel<<<dim3(8, 32), b>>>(Wv + wofs, WT + WT_V(l), 256, 1024);
            transpose_kernel<<<dim3(32, 8), b>>>(Wo + wofs, WT + WT_O(l), 1024, 256);
            fold_proj_kernel<<<NF, 256>>>(Wq + wofs, bq + (size_t)l * 1024, proj,
                                          WT + WQP(l), WT + BQP(l));
            fold_proj_kernel<<<NF, 256>>>(Wk + wofs, bk + (size_t)l * 1024, proj,
                                          WT + WKP(l), WT + BKP(l));
        }
    }

    const int MB = (NTOT + 127) / 128;
    const dim3 g256(2, MB);      // Nn = 256
    const dim3 g1024(8, MB);     // Nn = 1024
    const dim3 g120(1, MB);      // Nn = 120 (one 128-col tile)
    const dim3 gHead(MB, HEADS);

    gemm_tc<<<g256, 256, GEMM_SMEM>>>(x, WT + WT_IN, h, b_in, NTOT, 256, 256, 256, 0);
    gemm_tc<<<g256, 256, GEMM_SMEM>>>(H, WT + WT_HE, h, b_he, NTOT, 256, EDIM, 256, 1);

    for (int l = 0; l < LNUM; l++) {
        ln_elu_kernel<<<(NTOT + 7) / 8, 256>>>(h, ln_g + l * DM, ln_b + l * DM, z);

        // Qp/Kp = exp(z @ Wq' + bq') + 1e-6   (FAVOR+ fused)
        gemm_tc<<<g120, 256, GEMM_SMEM>>>(z, WT + WQP(l), Qp, WT + BQP(l),
                                          NTOT, NF, 256, NF, 2);
        gemm_tc<<<g120, 256, GEMM_SMEM>>>(z, WT + WKP(l), Kp, WT + BKP(l),
                                          NTOT, NF, 256, NF, 2);
        // V = z @ Wv + bv
        gemm_tc<<<g1024, 256, GEMM_SMEM>>>(z, WT + WT_V(l), V, bv + (size_t)l * 1024,
                                           NTOT, 1024, 256, 1024, 0);

        zero_kv_kernel<<<(HEADS * MF * DM + 255) / 256, 256>>>();
        kv_kernel<<<gHead, 256>>>(Kp, V);
        z_kernel<<<gHead, 256>>>(Qp, Zb);

        // h += Z @ Wo + bo
        gemm_tc<<<g256, 256, GEMM_SMEM>>>(Zb, WT + WT_O(l), h, bo + (size_t)l * DM,
                                          NTOT, 256, 1024, 256, 1);
    }
}